// round 15
// baseline (speedup 1.0000x reference)
#include <cuda_runtime.h>
#include <cuda_fp16.h>
#include <math.h>

#define NN 50000
#define EE 1600000
#define GG 64
#define HID 64
#define NH 4
#define CH 16
#define NIN 32
#define EIN 16

// ---------------- scratch (device globals; no allocation allowed) ----------
__device__ __align__(16) float  g_h[NN * HID];
__device__ __align__(16) float  g_q[NN * HID];
__device__ __align__(16) float  g_skip[NN * HID];
__device__ __align__(16) float  g_qe[NN * HID];
__device__ __align__(16) __half g_kvh[(size_t)NN * 128];    // per node: k[64] then v[64], fp16
__device__ __align__(16) __half g_eash[(size_t)EE * EIN];   // ea, dst-sorted, fp16
__device__ int   g_src[EE];
__device__ int   g_deg[NN];
__device__ int   g_off[NN + 1];
__device__ int   g_ctr[NN];
__device__ int   g_part[256];
__device__ int   g_partpre[256];
__device__ __align__(16) float g_pool[GG * HID];
__device__ float g_cnt[GG];

__device__ __forceinline__ void red_add_v4(float* p, float4 v) {
    asm volatile("red.global.add.v4.f32 [%0], {%1,%2,%3,%4};"
                 :: "l"(p), "f"(v.x), "f"(v.y), "f"(v.z), "f"(v.w) : "memory");
}
__device__ __forceinline__ void red_add_f(float* p, float v) {
    asm volatile("red.global.add.f32 [%0], %1;" :: "l"(p), "f"(v) : "memory");
}
__device__ __forceinline__ void fma2(unsigned long long& d,
                                     unsigned long long a, unsigned long long b) {
    asm("fma.rn.f32x2 %0, %1, %2, %0;" : "+l"(d) : "l"(a), "l"(b));
}
__device__ __forceinline__ unsigned long long pack2(float lo, float hi) {
    unsigned long long r;
    asm("mov.b64 %0, {%1, %2};" : "=l"(r) : "f"(lo), "f"(hi));
    return r;
}
__device__ __forceinline__ float unpack_sum(unsigned long long v) {
    float lo, hi;
    asm("mov.b64 {%0, %1}, %2;" : "=f"(lo), "=f"(hi) : "l"(v));
    return lo + hi;
}

// ---------------- input layer: h = relu(x @ Wn + bn) ------------------------
__global__ void k_input(const float* __restrict__ x,
                        const float* __restrict__ Wn,
                        const float* __restrict__ bn) {
    __shared__ float sW[NIN * HID];
    __shared__ float sx[16][NIN + 2];
    __shared__ float sb[HID];
    int t = threadIdx.x;
    for (int i = t; i < NIN * HID; i += 256) sW[i] = Wn[i];
    if (t < HID) sb[t] = bn[t];
    int nb = blockIdx.x * 16;
    for (int i = t; i < 16 * NIN; i += 256) {
        int r = i / NIN, c = i % NIN;
        sx[r][c] = x[(nb + r) * NIN + c];
    }
    __syncthreads();
    int cw = t & 15;
    int r  = t >> 4;
    int n  = nb + r;
    float a0 = sb[cw*4], a1 = sb[cw*4+1], a2 = sb[cw*4+2], a3 = sb[cw*4+3];
#pragma unroll
    for (int i = 0; i < NIN; i++) {
        float hv = sx[r][i];
        float4 w = *(const float4*)&sW[i * HID + cw * 4];
        a0 += hv * w.x; a1 += hv * w.y; a2 += hv * w.z; a3 += hv * w.w;
    }
    float4 o = make_float4(fmaxf(a0,0.f), fmaxf(a1,0.f), fmaxf(a2,0.f), fmaxf(a3,0.f));
    *(float4*)&g_h[n * HID + cw * 4] = o;
}

// ---------------- CSR sort by dst -------------------------------------------
__global__ void k_zerodeg() {
    int i = blockIdx.x * 256 + threadIdx.x;
    if (i < NN) g_deg[i] = 0;
}
__global__ void k_hist(const int* __restrict__ ei) {
    int e = blockIdx.x * 256 + threadIdx.x;
    atomicAdd(&g_deg[ei[EE + e]], 1);
}
__global__ void k_scanA() {
    __shared__ int sp[256];
    int t = threadIdx.x, i = blockIdx.x * 256 + t;
    int d = (i < NN) ? g_deg[i] : 0;
    sp[t] = d; __syncthreads();
    for (int off = 128; off; off >>= 1) {
        if (t < off) sp[t] += sp[t + off];
        __syncthreads();
    }
    if (t == 0) g_part[blockIdx.x] = sp[0];
}
__global__ void k_scanB(int nparts) {
    __shared__ int sp[256];
    int t = threadIdx.x;
    int v = (t < nparts) ? g_part[t] : 0;
    sp[t] = v; __syncthreads();
    for (int off = 1; off < 256; off <<= 1) {
        int u = (t >= off) ? sp[t - off] : 0;
        __syncthreads();
        sp[t] += u;
        __syncthreads();
    }
    g_partpre[t] = sp[t] - v;   // exclusive
}
__global__ void k_scanC() {
    __shared__ int sp[256];
    int t = threadIdx.x, b = blockIdx.x, i = b * 256 + t;
    int d = (i < NN) ? g_deg[i] : 0;
    sp[t] = d; __syncthreads();
    for (int off = 1; off < 256; off <<= 1) {
        int u = (t >= off) ? sp[t - off] : 0;
        __syncthreads();
        sp[t] += u;
        __syncthreads();
    }
    int off0 = g_partpre[b] + sp[t] - d;   // exclusive
    if (i < NN) { g_off[i] = off0; g_ctr[i] = off0; }
    if (b == 0 && t == 0) g_off[NN] = EE;
}
__global__ void k_scatter(const int* __restrict__ ei, const float* __restrict__ ea) {
    long tid = (long)blockIdx.x * 256 + threadIdx.x;
    long e = tid >> 2;
    int  j = (int)(tid & 3);
    int lane = threadIdx.x & 31;
    int pos = 0;
    if (j == 0) {
        int d = ei[EE + e];
        pos = atomicAdd(&g_ctr[d], 1);
        g_src[pos] = ei[e];
    }
    pos = __shfl_sync(0xffffffffu, pos, lane & ~3);
    float4 v = ((const float4*)&ea[(size_t)e * EIN])[j];
    __half2 p0 = __float22half2_rn(make_float2(v.x, v.y));
    __half2 p1 = __float22half2_rn(make_float2(v.z, v.w));
    size_t base = (size_t)pos * EIN + j * 4;
    *(__half2*)&g_eash[base]     = p0;
    *(__half2*)&g_eash[base + 2] = p1;
}

// ---------------- per-layer node linears: q,k,v,skip + qe (fused) -----------
// dyn smem: sW2[4*4096] (i-interleaved pairs) + sb[256] + sh[16*68] + sWe[1024]
__global__ void k_qkvs(const float* __restrict__ Wq, const float* __restrict__ bq,
                       const float* __restrict__ Wk, const float* __restrict__ bk,
                       const float* __restrict__ Wv, const float* __restrict__ bv,
                       const float* __restrict__ Ws, const float* __restrict__ bs,
                       const float* __restrict__ We) {
    extern __shared__ float sm[];
    float* sW2 = sm;                    // 16384 (also aliased as sq later)
    float* sb  = sm + 16384;            // 256
    float* sh  = sm + 16640;            // 16*68
    float* sWe = sm + 17728;            // 1024
    int t = threadIdx.x;
    const float* Wp[4] = {Wq, Wk, Wv, Ws};
    const float* bp[4] = {bq, bk, bv, bs};
#pragma unroll
    for (int a0 = 0; a0 < 4; a0++)
        for (int idx = t; idx < 4096; idx += 256) {
            int i = idx >> 6, c = idx & 63;
            sW2[a0 * 4096 + ((i >> 1) << 7) + (c << 1) + (i & 1)] = Wp[a0][idx];
        }
    sb[t] = bp[t >> 6][t & 63];
    for (int i = t; i < 1024; i += 256) sWe[i] = We[i];
    int nb = blockIdx.x * 16;
    for (int i = t; i < 16 * HID; i += 256) {
        int r = i >> 6, c = i & 63;
        sh[r * 68 + c] = g_h[(nb + r) * HID + c];
    }
    __syncthreads();

    int a  = t >> 6;          // array: 0=q 1=k 2=v 3=skip
    int cw = t & 15;          // 4-col group
    int nq = (t >> 4) & 3;    // 4-node group
    unsigned long long acc2[4][4];
#pragma unroll
    for (int m = 0; m < 4; m++)
#pragma unroll
        for (int c = 0; c < 4; c++)
            acc2[m][c] = pack2(sb[a * 64 + cw * 4 + c], 0.f);
    const float* wbase = &sW2[a * 4096 + cw * 8];
#pragma unroll 4
    for (int i2 = 0; i2 < 32; i2++) {
        ulonglong2 w01 = *(const ulonglong2*)&wbase[i2 * 128];
        ulonglong2 w23 = *(const ulonglong2*)&wbase[i2 * 128 + 4];
#pragma unroll
        for (int m = 0; m < 4; m++) {
            unsigned long long hv =
                *(const unsigned long long*)&sh[(nq * 4 + m) * 68 + i2 * 2];
            fma2(acc2[m][0], hv, w01.x);
            fma2(acc2[m][1], hv, w01.y);
            fma2(acc2[m][2], hv, w23.x);
            fma2(acc2[m][3], hv, w23.y);
        }
    }
    float o[4][4];
#pragma unroll
    for (int m = 0; m < 4; m++)
#pragma unroll
        for (int c = 0; c < 4; c++) o[m][c] = unpack_sum(acc2[m][c]);

    if (a == 1 || a == 2) {
        // k or v -> fp16 interleaved g_kvh (k at 0, v at 64)
        int voff = (a == 2) ? 64 : 0;
#pragma unroll
        for (int m = 0; m < 4; m++) {
            __half2 p0 = __float22half2_rn(make_float2(o[m][0], o[m][1]));
            __half2 p1 = __float22half2_rn(make_float2(o[m][2], o[m][3]));
            __half2* dst = (__half2*)&g_kvh[(size_t)(nb + nq * 4 + m) * 128 + voff + cw * 4];
            dst[0] = p0; dst[1] = p1;
        }
    } else {
        float* outp = (a == 0) ? g_q : g_skip;
#pragma unroll
        for (int m = 0; m < 4; m++)
            *(float4*)&outp[(nb + nq * 4 + m) * HID + cw * 4] =
                make_float4(o[m][0], o[m][1], o[m][2], o[m][3]);
    }
    __syncthreads();
    // stage q into sq (alias sW2[0..1024)) for qe
    float* sq = sm;
    if (a == 0)
#pragma unroll
        for (int m = 0; m < 4; m++)
#pragma unroll
            for (int c = 0; c < 4; c++)
                sq[(nq * 4 + m) * 64 + cw * 4 + c] = o[m][c];
    __syncthreads();
    // qe[n, h*16+i0] = sum_c We[i0, h*16+c] * q[n, h*16+c]
#pragma unroll
    for (int kk = 0; kk < 4; kk++) {
        int oo = t + 256 * kk;
        int r = oo >> 6, j = oo & 63, h = j >> 4, i0 = j & 15;
        float s = 0.f;
#pragma unroll
        for (int c = 0; c < CH; c++)
            s += sWe[i0 * HID + h * CH + c] * sq[r * 64 + h * CH + c];
        g_qe[(nb + r) * HID + j] = s;
    }
}

// ---------------- fused edge pass: online softmax + aggregate + update ------
// TWO warps per dst node (wp=0/1), 4 nodes per 256-thread block.
// Within a warp: 4 edge-slots (g) x 8 lanes (u); the pair covers 8 edge
// slots per iteration with stride 8. Lane u owns cols c0=8u..8u+7
// (head h=u>>1, ea-half=u&1). Branchless 2-deep pipeline as before.
// Pair merge via smem + named barrier scoped to the 64-thread pair.
__global__ void __launch_bounds__(256, 3) k_edge(const float* __restrict__ We) {
    __shared__ float sWe[EIN * HID];
    __shared__ float s_e[4][4][16];     // [node][head][ea]
    __shared__ float s_den[4][4];
    __shared__ float s_vacc1[4][64];    // wp1 partial vacc
    __shared__ float s_eacc1[4][64];    // wp1 partial eacc ([head][16])
    __shared__ float s_md[4][8];        // wp1 (m,den) per head
    int t = threadIdx.x;
    for (int i = t; i < EIN * HID; i += 256) sWe[i] = We[i];
    __syncthreads();
    int wid = t >> 5, lane = t & 31;
    int nd = wid >> 1;                 // node slot in block (0..3)
    int wp = wid & 1;                  // warp within pair
    int n = blockIdx.x * 4 + nd;       // grid = 12500, exact
    int g = lane >> 3, u = lane & 7;
    int h = u >> 1, half = u & 1;
    int c0 = u * 8;                    // owned column range
    int begin = g_off[n], end = g_off[n + 1];
    int base = begin + wp * 4;
    int nIter = (end - base + 7) >> 3;   // per-warp uniform (>=0 arithmetically)

    float q[8], qe[8];
    {
        const float4* qp  = (const float4*)&g_q [(size_t)n * HID + c0];
        const float4* qep = (const float4*)&g_qe[(size_t)n * HID + c0];
        float4 a0 = qp[0], a1 = qp[1], b0 = qep[0], b1 = qep[1];
        q[0]=a0.x; q[1]=a0.y; q[2]=a0.z; q[3]=a0.w;
        q[4]=a1.x; q[5]=a1.y; q[6]=a1.z; q[7]=a1.w;
        qe[0]=b0.x; qe[1]=b0.y; qe[2]=b0.z; qe[3]=b0.w;
        qe[4]=b1.x; qe[5]=b1.y; qe[6]=b1.z; qe[7]=b1.w;
    }

    float m = -1e30f, den = 0.f;
    float vacc[8] = {}, eacc[8] = {};

    if (nIter > 0) {
        int last = end - 1;
        int pc0 = min(base + g, last);
        int s0 = g_src[pc0];
        uint4 eaq = __ldcs((const uint4*)&g_eash[(size_t)pc0 * EIN + half * 8]);
        const uint4* kvp0 = (const uint4*)&g_kvh[(size_t)s0 * 128];
        uint4 kh = kvp0[u];
        uint4 vh = kvp0[8 + u];
        int pc1 = min(base + 8 + g, last);
        int s1 = g_src[pc1];
        uint4 ea1 = __ldcs((const uint4*)&g_eash[(size_t)pc1 * EIN + half * 8]);
        for (int it = 0; it < nIter; it++) {
            const uint4* kvp = (const uint4*)&g_kvh[(size_t)s1 * 128];
            uint4 kh_n = kvp[u];
            uint4 vh_n = kvp[8 + u];
            int pc2 = min(base + (it + 2) * 8 + g, last);
            int s2 = g_src[pc2];
            uint4 ea2 = __ldcs((const uint4*)&g_eash[(size_t)pc2 * EIN + half * 8]);

            int pos = base + it * 8 + g;
            bool valid = pos < end;
            float kf[8], vf[8], eaf[8];
            {
                __half2* kp2 = (__half2*)&kh;
                __half2* vp2 = (__half2*)&vh;
                __half2* ep2 = (__half2*)&eaq;
#pragma unroll
                for (int i = 0; i < 4; i++) {
                    float2 kk = __half22float2(kp2[i]);
                    float2 vv = __half22float2(vp2[i]);
                    float2 ee = __half22float2(ep2[i]);
                    kf[i*2] = kk.x; kf[i*2+1] = kk.y;
                    vf[i*2] = vv.x; vf[i*2+1] = vv.y;
                    eaf[i*2] = ee.x; eaf[i*2+1] = ee.y;
                }
            }
            float p = 0.f;
#pragma unroll
            for (int i = 0; i < 8; i++) p += q[i] * kf[i] + qe[i] * eaf[i];
            p += __shfl_xor_sync(0xffffffffu, p, 1);   // combine head halves
            if (valid) {
                float alpha = p * 0.25f;
                float nm = fmaxf(m, alpha);
                float sc = __expf(m - nm);
                float ex = __expf(alpha - nm);
                m = nm;
                den = den * sc + ex;
#pragma unroll
                for (int i = 0; i < 8; i++) {
                    vacc[i] = vacc[i] * sc + ex * vf[i];
                    eacc[i] = eacc[i] * sc + ex * eaf[i];
                }
            }
            kh = kh_n; vh = vh_n; eaq = ea1;
            s1 = s2; ea1 = ea2;
        }
    }

    // intra-warp merge of the 4 edge-slot groups
#pragma unroll
    for (int off = 8; off <= 16; off <<= 1) {
        float m2 = __shfl_xor_sync(0xffffffffu, m, off);
        float d2 = __shfl_xor_sync(0xffffffffu, den, off);
        float nm = fmaxf(m, m2);
        float s1 = __expf(m - nm), s2 = __expf(m2 - nm);
        den = den * s1 + d2 * s2;
#pragma unroll
        for (int i = 0; i < 8; i++) {
            float v2 = __shfl_xor_sync(0xffffffffu, vacc[i], off);
            vacc[i] = vacc[i] * s1 + v2 * s2;
            float e2 = __shfl_xor_sync(0xffffffffu, eacc[i], off);
            eacc[i] = eacc[i] * s1 + e2 * s2;
        }
        m = nm;
    }

    // wp1 publishes its partial state for the pair merge
    if (wp == 1 && g == 0) {
#pragma unroll
        for (int i = 0; i < 8; i++) {
            s_vacc1[nd][c0 + i] = vacc[i];
            s_eacc1[nd][h * 16 + half * 8 + i] = eacc[i];
        }
        if (half == 0) { s_md[nd][h * 2] = m; s_md[nd][h * 2 + 1] = den; }
    }
    // named barrier scoped to this 64-thread pair (ids 1..4)
    asm volatile("bar.sync %0, %1;" :: "r"(nd + 1), "r"(64) : "memory");

    if (wp == 0 && g == 0) {
        // pair merge: combine wp1's partials into this warp's registers
        float m2 = s_md[nd][h * 2];
        float d2 = s_md[nd][h * 2 + 1];
        float nm = fmaxf(m, m2);
        float s1 = __expf(m - nm), s2 = __expf(m2 - nm);
        den = den * s1 + d2 * s2;
#pragma unroll
        for (int i = 0; i < 8; i++) {
            vacc[i] = vacc[i] * s1 + s_vacc1[nd][c0 + i] * s2;
            eacc[i] = eacc[i] * s1 + s_eacc1[nd][h * 16 + half * 8 + i] * s2;
        }
        // stage merged eacc/den for the et GEMV (cross-half read)
#pragma unroll
        for (int i = 0; i < 8; i++) s_e[nd][h][half * 8 + i] = eacc[i];
        if (half == 0) s_den[nd][h] = den;
    }
    __syncwarp();

    if (wp == 0 && g == 0) {
        float inv = 1.f / (s_den[nd][h] + 1e-16f);
        float et[8] = {};
#pragma unroll
        for (int j = 0; j < EIN; j++) {
            float ev = s_e[nd][h][j];
            float4 w0 = *(const float4*)&sWe[j * HID + c0];
            float4 w1 = *(const float4*)&sWe[j * HID + c0 + 4];
            et[0] += ev * w0.x; et[1] += ev * w0.y;
            et[2] += ev * w0.z; et[3] += ev * w0.w;
            et[4] += ev * w1.x; et[5] += ev * w1.y;
            et[6] += ev * w1.z; et[7] += ev * w1.w;
        }
        size_t bb = (size_t)n * HID + c0;
        float4 sk0 = *(const float4*)&g_skip[bb];
        float4 sk1 = *(const float4*)&g_skip[bb + 4];
        float4 hv0 = *(float4*)&g_h[bb];
        float4 hv1 = *(float4*)&g_h[bb + 4];
        hv0.x += fmaxf((vacc[0] + et[0]) * inv + sk0.x, 0.f);
        hv0.y += fmaxf((vacc[1] + et[1]) * inv + sk0.y, 0.f);
        hv0.z += fmaxf((vacc[2] + et[2]) * inv + sk0.z, 0.f);
        hv0.w += fmaxf((vacc[3] + et[3]) * inv + sk0.w, 0.f);
        hv1.x += fmaxf((vacc[4] + et[4]) * inv + sk1.x, 0.f);
        hv1.y += fmaxf((vacc[5] + et[5]) * inv + sk1.y, 0.f);
        hv1.z += fmaxf((vacc[6] + et[6]) * inv + sk1.z, 0.f);
        hv1.w += fmaxf((vacc[7] + et[7]) * inv + sk1.w, 0.f);
        *(float4*)&g_h[bb] = hv0;
        *(float4*)&g_h[bb + 4] = hv1;
    }
}

// ---------------- pooling + MLP ---------------------------------------------
__global__ void k_poolzero() {
    int t = threadIdx.x;
    for (int i = t; i < GG * HID; i += 256) g_pool[i] = 0.f;
    if (t < GG) g_cnt[t] = 0.f;
}
__global__ void k_pool(const int* __restrict__ batch) {
    long idx = (long)blockIdx.x * 256 + threadIdx.x;
    int n = (int)(idx >> 4), cg = (int)(idx & 15);
    if (n >= NN) return;
    int b = batch[n];
    float4 hv = *(const float4*)&g_h[n * HID + cg * 4];
    red_add_v4(&g_pool[b * HID + cg * 4], hv);
    if (cg == 0) red_add_f(&g_cnt[b], 1.f);
}
__global__ void k_mlp(const float* __restrict__ W1, const float* __restrict__ b1,
                      const float* __restrict__ W2, const float* __restrict__ b2,
                      float* __restrict__ out) {
    __shared__ float sm[HID];
    int g = blockIdx.x, t = threadIdx.x;
    float cnt = fmaxf(g_cnt[g], 1.f);
    sm[t] = g_pool[g * HID + t] / cnt;
    __syncthreads();
    if (t < 32) {
        float r = b1[t];
#pragma unroll
        for (int i = 0; i < HID; i++) r += sm[i] * W1[i * 32 + t];
        r = fmaxf(r, 0.f) * W2[t];
#pragma unroll
        for (int o = 16; o; o >>= 1) r += __shfl_down_sync(0xffffffffu, r, o);
        if (t == 0) out[g] = r + b2[0];
    }
}

// ---------------- launch ----------------------------------------------------
extern "C" void kernel_launch(void* const* d_in, const int* in_sizes, int n_in,
                              void* d_out, int out_size) {
    const float* x   = (const float*)d_in[0];
    const int*   ei  = (const int*)d_in[1];
    const float* ea  = (const float*)d_in[2];
    const int*   bat = (const int*)d_in[3];
    const float* Wn  = (const float*)d_in[4];
    const float* bn  = (const float*)d_in[5];
    const float* Wq  = (const float*)d_in[6];
    const float* bq  = (const float*)d_in[7];
    const float* Wk  = (const float*)d_in[8];
    const float* bk  = (const float*)d_in[9];
    const float* Wv  = (const float*)d_in[10];
    const float* bv  = (const float*)d_in[11];
    const float* We  = (const float*)d_in[12];
    const float* Ws  = (const float*)d_in[13];
    const float* bs  = (const float*)d_in[14];
    const float* W1  = (const float*)d_in[15];
    const float* b1  = (const float*)d_in[16];
    const float* W2  = (const float*)d_in[17];
    const float* b2  = (const float*)d_in[18];
    float* out = (float*)d_out;

    const int QKVS_SMEM = (4 * 4096 + 256 + 16 * 68 + 1024) * (int)sizeof(float); // 75008
    cudaFuncSetAttribute(k_qkvs, cudaFuncAttributeMaxDynamicSharedMemorySize, QKVS_SMEM);

    const int NODE_BLOCKS = NN / 16;          // 3125 (exact)
    const int SCAN_BLOCKS = (NN + 255) / 256; // 196
    const int EDGE1T      = EE / 256;         // 6250
    const int EDGE4T      = EE * 4 / 256;     // 25000

    // CSR sort (once per launch, reused by all 3 layers)
    k_zerodeg<<<SCAN_BLOCKS, 256>>>();
    k_hist<<<EDGE1T, 256>>>(ei);
    k_scanA<<<SCAN_BLOCKS, 256>>>();
    k_scanB<<<1, 256>>>(SCAN_BLOCKS);
    k_scanC<<<SCAN_BLOCKS, 256>>>();
    k_scatter<<<EDGE4T, 256>>>(ei, ea);

    k_input<<<NODE_BLOCKS, 256>>>(x, Wn, bn);
    for (int l = 0; l < 3; l++) {
        k_qkvs<<<NODE_BLOCKS, 256, QKVS_SMEM>>>(
            Wq + l * HID * HID, bq + l * HID,
            Wk + l * HID * HID, bk + l * HID,
            Wv + l * HID * HID, bv + l * HID,
            Ws + l * HID * HID, bs + l * HID,
            We + l * EIN * HID);
        k_edge<<<NN / 4, 256>>>(We + l * EIN * HID);
    }
    k_poolzero<<<1, 256>>>();
    k_pool<<<NODE_BLOCKS, 256>>>(bat);
    k_mlp<<<GG, 64>>>(W1, b1, W2, b2, out);
}

// round 17
// speedup vs baseline: 1.1303x; 1.1303x over previous
#include <cuda_runtime.h>
#include <cuda_fp16.h>
#include <math.h>

#define NN 50000
#define EE 1600000
#define GG 64
#define HID 64
#define NH 4
#define CH 16
#define NIN 32
#define EIN 16

// ---------------- scratch (device globals; no allocation allowed) ----------
__device__ __align__(16) float  g_h[NN * HID];
__device__ __align__(16) float  g_q[NN * HID];
__device__ __align__(16) float  g_skip[NN * HID];
__device__ __align__(16) float  g_qe[NN * HID];
__device__ __align__(16) __half g_kvh[(size_t)NN * 128];    // per node: k[64] then v[64], fp16
__device__ __align__(16) __half g_eash[(size_t)EE * EIN];   // ea, dst-sorted, fp16
__device__ int   g_src[EE];
__device__ int   g_deg[NN];
__device__ int   g_off[NN + 1];
__device__ int   g_ctr[NN];
__device__ int   g_part[256];
__device__ int   g_partpre[256];
__device__ __align__(16) float g_pool[GG * HID];
__device__ float g_cnt[GG];

__device__ __forceinline__ void red_add_v4(float* p, float4 v) {
    asm volatile("red.global.add.v4.f32 [%0], {%1,%2,%3,%4};"
                 :: "l"(p), "f"(v.x), "f"(v.y), "f"(v.z), "f"(v.w) : "memory");
}
__device__ __forceinline__ void red_add_f(float* p, float v) {
    asm volatile("red.global.add.f32 [%0], %1;" :: "l"(p), "f"(v) : "memory");
}
__device__ __forceinline__ void fma2(unsigned long long& d,
                                     unsigned long long a, unsigned long long b) {
    asm("fma.rn.f32x2 %0, %1, %2, %0;" : "+l"(d) : "l"(a), "l"(b));
}
__device__ __forceinline__ unsigned long long pack2(float lo, float hi) {
    unsigned long long r;
    asm("mov.b64 %0, {%1, %2};" : "=l"(r) : "f"(lo), "f"(hi));
    return r;
}
__device__ __forceinline__ float unpack_sum(unsigned long long v) {
    float lo, hi;
    asm("mov.b64 {%0, %1}, %2;" : "=f"(lo), "=f"(hi) : "l"(v));
    return lo + hi;
}

// ---------------- input layer: h = relu(x @ Wn + bn) ------------------------
__global__ void k_input(const float* __restrict__ x,
                        const float* __restrict__ Wn,
                        const float* __restrict__ bn) {
    __shared__ float sW[NIN * HID];
    __shared__ float sx[16][NIN + 2];
    __shared__ float sb[HID];
    int t = threadIdx.x;
    for (int i = t; i < NIN * HID; i += 256) sW[i] = Wn[i];
    if (t < HID) sb[t] = bn[t];
    int nb = blockIdx.x * 16;
    for (int i = t; i < 16 * NIN; i += 256) {
        int r = i / NIN, c = i % NIN;
        sx[r][c] = x[(nb + r) * NIN + c];
    }
    __syncthreads();
    int cw = t & 15;
    int r  = t >> 4;
    int n  = nb + r;
    float a0 = sb[cw*4], a1 = sb[cw*4+1], a2 = sb[cw*4+2], a3 = sb[cw*4+3];
#pragma unroll
    for (int i = 0; i < NIN; i++) {
        float hv = sx[r][i];
        float4 w = *(const float4*)&sW[i * HID + cw * 4];
        a0 += hv * w.x; a1 += hv * w.y; a2 += hv * w.z; a3 += hv * w.w;
    }
    float4 o = make_float4(fmaxf(a0,0.f), fmaxf(a1,0.f), fmaxf(a2,0.f), fmaxf(a3,0.f));
    *(float4*)&g_h[n * HID + cw * 4] = o;
}

// ---------------- CSR sort by dst -------------------------------------------
__global__ void k_zerodeg() {
    int i = blockIdx.x * 256 + threadIdx.x;
    if (i < NN) g_deg[i] = 0;
}
__global__ void k_hist(const int* __restrict__ ei) {
    int e = blockIdx.x * 256 + threadIdx.x;
    atomicAdd(&g_deg[ei[EE + e]], 1);
}
__global__ void k_scanA() {
    __shared__ int sp[256];
    int t = threadIdx.x, i = blockIdx.x * 256 + t;
    int d = (i < NN) ? g_deg[i] : 0;
    sp[t] = d; __syncthreads();
    for (int off = 128; off; off >>= 1) {
        if (t < off) sp[t] += sp[t + off];
        __syncthreads();
    }
    if (t == 0) g_part[blockIdx.x] = sp[0];
}
__global__ void k_scanB(int nparts) {
    __shared__ int sp[256];
    int t = threadIdx.x;
    int v = (t < nparts) ? g_part[t] : 0;
    sp[t] = v; __syncthreads();
    for (int off = 1; off < 256; off <<= 1) {
        int u = (t >= off) ? sp[t - off] : 0;
        __syncthreads();
        sp[t] += u;
        __syncthreads();
    }
    g_partpre[t] = sp[t] - v;   // exclusive
}
__global__ void k_scanC() {
    __shared__ int sp[256];
    int t = threadIdx.x, b = blockIdx.x, i = b * 256 + t;
    int d = (i < NN) ? g_deg[i] : 0;
    sp[t] = d; __syncthreads();
    for (int off = 1; off < 256; off <<= 1) {
        int u = (t >= off) ? sp[t - off] : 0;
        __syncthreads();
        sp[t] += u;
        __syncthreads();
    }
    int off0 = g_partpre[b] + sp[t] - d;   // exclusive
    if (i < NN) { g_off[i] = off0; g_ctr[i] = off0; }
    if (b == 0 && t == 0) g_off[NN] = EE;
}
__global__ void k_scatter(const int* __restrict__ ei, const float* __restrict__ ea) {
    long tid = (long)blockIdx.x * 256 + threadIdx.x;
    long e = tid >> 2;
    int  j = (int)(tid & 3);
    int lane = threadIdx.x & 31;
    int pos = 0;
    if (j == 0) {
        int d = ei[EE + e];
        pos = atomicAdd(&g_ctr[d], 1);
        g_src[pos] = ei[e];
    }
    pos = __shfl_sync(0xffffffffu, pos, lane & ~3);
    float4 v = ((const float4*)&ea[(size_t)e * EIN])[j];
    __half2 p0 = __float22half2_rn(make_float2(v.x, v.y));
    __half2 p1 = __float22half2_rn(make_float2(v.z, v.w));
    size_t base = (size_t)pos * EIN + j * 4;
    *(__half2*)&g_eash[base]     = p0;
    *(__half2*)&g_eash[base + 2] = p1;
}

// ---------------- per-layer node linears: q,k,v,skip + qe (fused) -----------
// dyn smem: sW2[4*4096] (i-interleaved pairs) + sb[256] + sh[16*68] + sWe[1024]
__global__ void k_qkvs(const float* __restrict__ Wq, const float* __restrict__ bq,
                       const float* __restrict__ Wk, const float* __restrict__ bk,
                       const float* __restrict__ Wv, const float* __restrict__ bv,
                       const float* __restrict__ Ws, const float* __restrict__ bs,
                       const float* __restrict__ We) {
    extern __shared__ float sm[];
    float* sW2 = sm;                    // 16384 (also aliased as sq later)
    float* sb  = sm + 16384;            // 256
    float* sh  = sm + 16640;            // 16*68
    float* sWe = sm + 17728;            // 1024
    int t = threadIdx.x;
    const float* Wp[4] = {Wq, Wk, Wv, Ws};
    const float* bp[4] = {bq, bk, bv, bs};
#pragma unroll
    for (int a0 = 0; a0 < 4; a0++)
        for (int idx = t; idx < 4096; idx += 256) {
            int i = idx >> 6, c = idx & 63;
            sW2[a0 * 4096 + ((i >> 1) << 7) + (c << 1) + (i & 1)] = Wp[a0][idx];
        }
    sb[t] = bp[t >> 6][t & 63];
    for (int i = t; i < 1024; i += 256) sWe[i] = We[i];
    int nb = blockIdx.x * 16;
    for (int i = t; i < 16 * HID; i += 256) {
        int r = i >> 6, c = i & 63;
        sh[r * 68 + c] = g_h[(nb + r) * HID + c];
    }
    __syncthreads();

    int a  = t >> 6;          // array: 0=q 1=k 2=v 3=skip
    int cw = t & 15;          // 4-col group
    int nq = (t >> 4) & 3;    // 4-node group
    unsigned long long acc2[4][4];
#pragma unroll
    for (int m = 0; m < 4; m++)
#pragma unroll
        for (int c = 0; c < 4; c++)
            acc2[m][c] = pack2(sb[a * 64 + cw * 4 + c], 0.f);
    const float* wbase = &sW2[a * 4096 + cw * 8];
#pragma unroll 4
    for (int i2 = 0; i2 < 32; i2++) {
        ulonglong2 w01 = *(const ulonglong2*)&wbase[i2 * 128];
        ulonglong2 w23 = *(const ulonglong2*)&wbase[i2 * 128 + 4];
#pragma unroll
        for (int m = 0; m < 4; m++) {
            unsigned long long hv =
                *(const unsigned long long*)&sh[(nq * 4 + m) * 68 + i2 * 2];
            fma2(acc2[m][0], hv, w01.x);
            fma2(acc2[m][1], hv, w01.y);
            fma2(acc2[m][2], hv, w23.x);
            fma2(acc2[m][3], hv, w23.y);
        }
    }
    float o[4][4];
#pragma unroll
    for (int m = 0; m < 4; m++)
#pragma unroll
        for (int c = 0; c < 4; c++) o[m][c] = unpack_sum(acc2[m][c]);

    if (a == 1 || a == 2) {
        // k or v -> fp16 interleaved g_kvh (k at 0, v at 64)
        int voff = (a == 2) ? 64 : 0;
#pragma unroll
        for (int m = 0; m < 4; m++) {
            __half2 p0 = __float22half2_rn(make_float2(o[m][0], o[m][1]));
            __half2 p1 = __float22half2_rn(make_float2(o[m][2], o[m][3]));
            __half2* dst = (__half2*)&g_kvh[(size_t)(nb + nq * 4 + m) * 128 + voff + cw * 4];
            dst[0] = p0; dst[1] = p1;
        }
    } else {
        float* outp = (a == 0) ? g_q : g_skip;
#pragma unroll
        for (int m = 0; m < 4; m++)
            *(float4*)&outp[(nb + nq * 4 + m) * HID + cw * 4] =
                make_float4(o[m][0], o[m][1], o[m][2], o[m][3]);
    }
    __syncthreads();
    // stage q into sq (alias sW2[0..1024)) for qe
    float* sq = sm;
    if (a == 0)
#pragma unroll
        for (int m = 0; m < 4; m++)
#pragma unroll
            for (int c = 0; c < 4; c++)
                sq[(nq * 4 + m) * 64 + cw * 4 + c] = o[m][c];
    __syncthreads();
    // qe[n, h*16+i0] = sum_c We[i0, h*16+c] * q[n, h*16+c]
#pragma unroll
    for (int kk = 0; kk < 4; kk++) {
        int oo = t + 256 * kk;
        int r = oo >> 6, j = oo & 63, h = j >> 4, i0 = j & 15;
        float s = 0.f;
#pragma unroll
        for (int c = 0; c < CH; c++)
            s += sWe[i0 * HID + h * CH + c] * sq[r * 64 + h * CH + c];
        g_qe[(nb + r) * HID + j] = s;
    }
}

// ---------------- fused edge pass: plain-exp softmax + aggregate + update ---
// warp per dst node; 4 edge-slots (g) x 8 lanes (u). Lane u owns cols
// c0=8u..8u+7 (head h=u>>1, ea-half=u&1). Branchless 2-deep pipeline.
// NO online max: alpha is bounded (|alpha| << 80) so exp(alpha) is safe in
// fp32 and the final division normalizes — removes the serial nm/sc chain;
// the only loop-carried dep is one FMA per accumulator.
__global__ void __launch_bounds__(256, 3) k_edge(const float* __restrict__ We) {
    __shared__ float sWe[EIN * HID];
    __shared__ float s_e[8][4][16];
    __shared__ float s_den[8][4];
    int t = threadIdx.x;
    for (int i = t; i < EIN * HID; i += 256) sWe[i] = We[i];
    __syncthreads();
    int wid = t >> 5, lane = t & 31;
    int n = blockIdx.x * 8 + wid;      // grid = 6250, exact
    int g = lane >> 3, u = lane & 7;
    int h = u >> 1, half = u & 1;
    int c0 = u * 8;                    // owned column range
    int begin = g_off[n], end = g_off[n + 1];
    int nIter = (end - begin + 3) >> 2;   // warp-uniform

    float q[8], qe[8];
    {
        const float4* qp  = (const float4*)&g_q [(size_t)n * HID + c0];
        const float4* qep = (const float4*)&g_qe[(size_t)n * HID + c0];
        float4 a0 = qp[0], a1 = qp[1], b0 = qep[0], b1 = qep[1];
        q[0]=a0.x; q[1]=a0.y; q[2]=a0.z; q[3]=a0.w;
        q[4]=a1.x; q[5]=a1.y; q[6]=a1.z; q[7]=a1.w;
        qe[0]=b0.x; qe[1]=b0.y; qe[2]=b0.z; qe[3]=b0.w;
        qe[4]=b1.x; qe[5]=b1.y; qe[6]=b1.z; qe[7]=b1.w;
    }

    float den = 0.f;
    float vacc[8] = {}, eacc[8] = {};

    if (nIter > 0) {
        int last = end - 1;
        int pc0 = min(begin + g, last);
        int s0 = g_src[pc0];
        uint4 eaq = __ldcs((const uint4*)&g_eash[(size_t)pc0 * EIN + half * 8]);
        const uint4* kvp0 = (const uint4*)&g_kvh[(size_t)s0 * 128];
        uint4 kh = kvp0[u];
        uint4 vh = kvp0[8 + u];
        int pc1 = min(begin + 4 + g, last);
        int s1 = g_src[pc1];
        uint4 ea1 = __ldcs((const uint4*)&g_eash[(size_t)pc1 * EIN + half * 8]);
        for (int it = 0; it < nIter; it++) {
            const uint4* kvp = (const uint4*)&g_kvh[(size_t)s1 * 128];
            uint4 kh_n = kvp[u];
            uint4 vh_n = kvp[8 + u];
            int pc2 = min(begin + (it + 2) * 4 + g, last);
            int s2 = g_src[pc2];
            uint4 ea2 = __ldcs((const uint4*)&g_eash[(size_t)pc2 * EIN + half * 8]);

            int pos = begin + it * 4 + g;
            bool valid = pos < end;
            float kf[8], vf[8], eaf[8];
            {
                __half2* kp2 = (__half2*)&kh;
                __half2* vp2 = (__half2*)&vh;
                __half2* ep2 = (__half2*)&eaq;
#pragma unroll
                for (int i = 0; i < 4; i++) {
                    float2 kk = __half22float2(kp2[i]);
                    float2 vv = __half22float2(vp2[i]);
                    float2 ee = __half22float2(ep2[i]);
                    kf[i*2] = kk.x; kf[i*2+1] = kk.y;
                    vf[i*2] = vv.x; vf[i*2+1] = vv.y;
                    eaf[i*2] = ee.x; eaf[i*2+1] = ee.y;
                }
            }
            // 4-way partial-sum tree: short dependency chain
            float p0 = q[0]*kf[0] + qe[0]*eaf[0];
            float p1 = q[1]*kf[1] + qe[1]*eaf[1];
            float p2 = q[2]*kf[2] + qe[2]*eaf[2];
            float p3 = q[3]*kf[3] + qe[3]*eaf[3];
            p0 += q[4]*kf[4] + qe[4]*eaf[4];
            p1 += q[5]*kf[5] + qe[5]*eaf[5];
            p2 += q[6]*kf[6] + qe[6]*eaf[6];
            p3 += q[7]*kf[7] + qe[7]*eaf[7];
            float p = (p0 + p1) + (p2 + p3);
            p += __shfl_xor_sync(0xffffffffu, p, 1);   // combine head halves
            float ex = valid ? __expf(p * 0.25f) : 0.f;
            den += ex;
#pragma unroll
            for (int i = 0; i < 8; i++) {
                vacc[i] += ex * vf[i];
                eacc[i] += ex * eaf[i];
            }
            kh = kh_n; vh = vh_n; eaq = ea1;
            s1 = s2; ea1 = ea2;
        }
    }

    // merge the 4 edge-slot groups (plain sums)
#pragma unroll
    for (int off = 8; off <= 16; off <<= 1) {
        den += __shfl_xor_sync(0xffffffffu, den, off);
#pragma unroll
        for (int i = 0; i < 8; i++) {
            vacc[i] += __shfl_xor_sync(0xffffffffu, vacc[i], off);
            eacc[i] += __shfl_xor_sync(0xffffffffu, eacc[i], off);
        }
    }

    if (g == 0) {
#pragma unroll
        for (int i = 0; i < 8; i++) s_e[wid][h][half * 8 + i] = eacc[i];
        if (half == 0) s_den[wid][h] = den;
    }
    __syncwarp();

    if (g == 0) {
        float inv = 1.f / (s_den[wid][h] + 1e-16f);
        float et[8] = {};
#pragma unroll
        for (int j = 0; j < EIN; j++) {
            float ev = s_e[wid][h][j];
            float4 w0 = *(const float4*)&sWe[j * HID + c0];
            float4 w1 = *(const float4*)&sWe[j * HID + c0 + 4];
            et[0] += ev * w0.x; et[1] += ev * w0.y;
            et[2] += ev * w0.z; et[3] += ev * w0.w;
            et[4] += ev * w1.x; et[5] += ev * w1.y;
            et[6] += ev * w1.z; et[7] += ev * w1.w;
        }
        size_t base = (size_t)n * HID + c0;
        float4 sk0 = *(const float4*)&g_skip[base];
        float4 sk1 = *(const float4*)&g_skip[base + 4];
        float4 hv0 = *(float4*)&g_h[base];
        float4 hv1 = *(float4*)&g_h[base + 4];
        hv0.x += fmaxf((vacc[0] + et[0]) * inv + sk0.x, 0.f);
        hv0.y += fmaxf((vacc[1] + et[1]) * inv + sk0.y, 0.f);
        hv0.z += fmaxf((vacc[2] + et[2]) * inv + sk0.z, 0.f);
        hv0.w += fmaxf((vacc[3] + et[3]) * inv + sk0.w, 0.f);
        hv1.x += fmaxf((vacc[4] + et[4]) * inv + sk1.x, 0.f);
        hv1.y += fmaxf((vacc[5] + et[5]) * inv + sk1.y, 0.f);
        hv1.z += fmaxf((vacc[6] + et[6]) * inv + sk1.z, 0.f);
        hv1.w += fmaxf((vacc[7] + et[7]) * inv + sk1.w, 0.f);
        *(float4*)&g_h[base] = hv0;
        *(float4*)&g_h[base + 4] = hv1;
    }
}

// ---------------- pooling + MLP ---------------------------------------------
__global__ void k_poolzero() {
    int t = threadIdx.x;
    for (int i = t; i < GG * HID; i += 256) g_pool[i] = 0.f;
    if (t < GG) g_cnt[t] = 0.f;
}
__global__ void k_pool(const int* __restrict__ batch) {
    long idx = (long)blockIdx.x * 256 + threadIdx.x;
    int n = (int)(idx >> 4), cg = (int)(idx & 15);
    if (n >= NN) return;
    int b = batch[n];
    float4 hv = *(const float4*)&g_h[n * HID + cg * 4];
    red_add_v4(&g_pool[b * HID + cg * 4], hv);
    if (cg == 0) red_add_f(&g_cnt[b], 1.f);
}
__global__ void k_mlp(const float* __restrict__ W1, const float* __restrict__ b1,
                      const float* __restrict__ W2, const float* __restrict__ b2,
                      float* __restrict__ out) {
    __shared__ float sm[HID];
    int g = blockIdx.x, t = threadIdx.x;
    float cnt = fmaxf(g_cnt[g], 1.f);
    sm[t] = g_pool[g * HID + t] / cnt;
    __syncthreads();
    if (t < 32) {
        float r = b1[t];
#pragma unroll
        for (int i = 0; i < HID; i++) r += sm[i] * W1[i * 32 + t];
        r = fmaxf(r, 0.f) * W2[t];
#pragma unroll
        for (int o = 16; o; o >>= 1) r += __shfl_down_sync(0xffffffffu, r, o);
        if (t == 0) out[g] = r + b2[0];
    }
}

// ---------------- launch ----------------------------------------------------
extern "C" void kernel_launch(void* const* d_in, const int* in_sizes, int n_in,
                              void* d_out, int out_size) {
    const float* x   = (const float*)d_in[0];
    const int*   ei  = (const int*)d_in[1];
    const float* ea  = (const float*)d_in[2];
    const int*   bat = (const int*)d_in[3];
    const float* Wn  = (const float*)d_in[4];
    const float* bn  = (const float*)d_in[5];
    const float* Wq  = (const float*)d_in[6];
    const float* bq  = (const float*)d_in[7];
    const float* Wk  = (const float*)d_in[8];
    const float* bk  = (const float*)d_in[9];
    const float* Wv  = (const float*)d_in[10];
    const float* bv  = (const float*)d_in[11];
    const float* We  = (const float*)d_in[12];
    const float* Ws  = (const float*)d_in[13];
    const float* bs  = (const float*)d_in[14];
    const float* W1  = (const float*)d_in[15];
    const float* b1  = (const float*)d_in[16];
    const float* W2  = (const float*)d_in[17];
    const float* b2  = (const float*)d_in[18];
    float* out = (float*)d_out;

    const int QKVS_SMEM = (4 * 4096 + 256 + 16 * 68 + 1024) * (int)sizeof(float); // 75008
    cudaFuncSetAttribute(k_qkvs, cudaFuncAttributeMaxDynamicSharedMemorySize, QKVS_SMEM);

    const int NODE_BLOCKS = NN / 16;          // 3125 (exact)
    const int SCAN_BLOCKS = (NN + 255) / 256; // 196
    const int EDGE1T      = EE / 256;         // 6250
    const int EDGE4T      = EE * 4 / 256;     // 25000

    // CSR sort (once per launch, reused by all 3 layers)
    k_zerodeg<<<SCAN_BLOCKS, 256>>>();
    k_hist<<<EDGE1T, 256>>>(ei);
    k_scanA<<<SCAN_BLOCKS, 256>>>();
    k_scanB<<<1, 256>>>(SCAN_BLOCKS);
    k_scanC<<<SCAN_BLOCKS, 256>>>();
    k_scatter<<<EDGE4T, 256>>>(ei, ea);

    k_input<<<NODE_BLOCKS, 256>>>(x, Wn, bn);
    for (int l = 0; l < 3; l++) {
        k_qkvs<<<NODE_BLOCKS, 256, QKVS_SMEM>>>(
            Wq + l * HID * HID, bq + l * HID,
            Wk + l * HID * HID, bk + l * HID,
            Wv + l * HID * HID, bv + l * HID,
            Ws + l * HID * HID, bs + l * HID,
            We + l * EIN * HID);
        k_edge<<<NN / 8, 256>>>(We + l * EIN * HID);
    }
    k_poolzero<<<1, 256>>>();
    k_pool<<<NODE_BLOCKS, 256>>>(bat);
    k_mlp<<<GG, 64>>>(W1, b1, W2, b2, out);
}